// round 12
// baseline (speedup 1.0000x reference)
#include <cuda_runtime.h>
#include <cstdint>

// Skinny GEMM via mma.sync tf32, direct-LDG mainloop + software L2 prefetch.
// C[65536,40] = embs[65536,1024] @ Wall^T, Wall = packed [W_status;W_flight;0]
// R12 thesis: per-SM outstanding-miss capacity caps in-flight bytes, so the
// fix is lower latency per miss, not more parallelism. prefetch.global.L2
// (baseline PTX) runs 8 k-blocks ahead; one instr covers all 32 warp rows
// (lane l prefetches row tokw+l). A-misses become ~250cyc L2 hits.
// mt=2 fragment layout identical to R6 (proven). RZ tf32 bias corrected.

#define EMB    1024
#define NS     5
#define NF     30
#define NL     35
#define NROWS  40
#define OUTC   63
#define BM     128
#define LSTR   41
#define NTH    128
#define NKB    (EMB / 16)    // 64 k16 blocks
#define PFD    8             // prefetch distance in k16 blocks (512B ahead)

__device__ float Wall[NROWS * EMB];   // 160KB packed weights (+zero pad rows)

__global__ void pack_w_kernel(const float* __restrict__ Ws,
                              const float* __restrict__ Wf) {
    int i = blockIdx.x * blockDim.x + threadIdx.x;
    if (i < NROWS * EMB) {
        int row = i >> 10, col = i & (EMB - 1);
        float v = 0.0f;
        if (row < NS)      v = Ws[row * EMB + col];
        else if (row < NL) v = Wf[(row - NS) * EMB + col];
        Wall[i] = v;
    }
}

__device__ __forceinline__ void mma8(float* c, const uint32_t* a, const uint32_t* b) {
    asm volatile(
        "mma.sync.aligned.m16n8k8.row.col.f32.tf32.tf32.f32 "
        "{%0,%1,%2,%3}, {%4,%5,%6,%7}, {%8,%9}, {%0,%1,%2,%3};"
        : "+f"(c[0]), "+f"(c[1]), "+f"(c[2]), "+f"(c[3])
        : "r"(a[0]), "r"(a[1]), "r"(a[2]), "r"(a[3]), "r"(b[0]), "r"(b[1]));
}
__device__ __forceinline__ void pf_l2(const void* p) {
    asm volatile("prefetch.global.L2 [%0];" :: "l"(p));
}

__global__ __launch_bounds__(NTH, 4) void aux2_pf_kernel(
    const float* __restrict__ embs,
    const float* __restrict__ b_status,
    const float* __restrict__ b_flight,
    float* __restrict__ out,
    int ntok)
{
    __shared__ float Ls[BM * LSTR];   // 21KB, epilogue only

    const int tid  = threadIdx.x;
    const int wid  = tid >> 5;
    const int lane = tid & 31;
    const int g    = lane >> 2;     // 0..7
    const int t    = lane & 3;      // 0..3
    const long tokw = (long)blockIdx.x * BM + wid * 32;

    // A fragment pointers: rows tokw + r*8 + g, this lane's col 4t
    const float* Abase = embs + (tokw + g) * EMB + 4 * t;
    // per-lane prefetch pointer: lane l covers row tokw + l
    const char* pfbase = reinterpret_cast<const char*>(embs + (tokw + lane) * EMB);
    // B: packed Wall, rows nt*8 + g, col 4t (immediate offsets)
    const float* Bbase = Wall + g * EMB + 4 * t;

    float acc[2][5][4];
#pragma unroll
    for (int mt = 0; mt < 2; ++mt)
#pragma unroll
        for (int nt = 0; nt < 5; ++nt)
#pragma unroll
            for (int i = 0; i < 4; ++i) acc[mt][nt][i] = 0.0f;

    // warm the prefetch window: lines for kb = 0..PFD
#pragma unroll
    for (int kb = 0; kb < PFD; kb += 2)
        pf_l2(pfbase + kb * 64);

#pragma unroll 2
    for (int kb = 0; kb < NKB; ++kb) {
        // L2 prefetch one line (covers kb+PFD and kb+PFD+1) per pair
        if ((kb & 1) == 0 && kb + PFD < NKB)
            pf_l2(pfbase + (kb + PFD) * 64);

        // front-batched loads: 4 A + 5 B LDG.128
        uint4 a[4];
#pragma unroll
        for (int r = 0; r < 4; ++r)
            a[r] = *(const uint4*)(Abase + r * 8 * EMB + kb * 16);

        uint4 b[5];
#pragma unroll
        for (int nt = 0; nt < 5; ++nt)
            b[nt] = *(const uint4*)(Bbase + nt * 8 * EMB + kb * 16);

        // K-permutation: slots {t,t+4} = cols {4t,4t+1}; then {4t+2,4t+3}
        uint32_t af0[2][4] = {
            { a[0].x, a[1].x, a[0].y, a[1].y },
            { a[2].x, a[3].x, a[2].y, a[3].y } };
        uint32_t af1[2][4] = {
            { a[0].z, a[1].z, a[0].w, a[1].w },
            { a[2].z, a[3].z, a[2].w, a[3].w } };

#pragma unroll
        for (int nt = 0; nt < 5; ++nt) {
            uint32_t bf0[2] = { b[nt].x, b[nt].y };
            uint32_t bf1[2] = { b[nt].z, b[nt].w };
#pragma unroll
            for (int mt = 0; mt < 2; ++mt) {
                mma8(acc[mt][nt], af0[mt], bf0);
                mma8(acc[mt][nt], af1[mt], bf1);
            }
        }
    }

    // ---- epilogue: fragments -> logits smem ----
#pragma unroll
    for (int mt = 0; mt < 2; ++mt)
#pragma unroll
        for (int nt = 0; nt < 5; ++nt) {
            int r0 = wid * 32 + mt * 16 + g;
            int cc = nt * 8 + t * 2;
            if (cc < NL) {
                Ls[r0 * LSTR + cc]       = acc[mt][nt][0];
                Ls[(r0 + 8) * LSTR + cc] = acc[mt][nt][2];
            }
            if (cc + 1 < NL) {
                Ls[r0 * LSTR + cc + 1]       = acc[mt][nt][1];
                Ls[(r0 + 8) * LSTR + cc + 1] = acc[mt][nt][3];
            }
        }
    __syncthreads();

    // ---- per-thread dual softmax + store (thread tid = token) ----
    {
        const float corr = 1.000677f;   // tf32 RZ truncation bias compensation
        float sl[NS], fl[NF];
#pragma unroll
        for (int n = 0; n < NS; ++n) sl[n] = Ls[tid * LSTR + n] * corr + b_status[n];
#pragma unroll
        for (int n = 0; n < NF; ++n) fl[n] = Ls[tid * LSTR + NS + n] * corr + b_flight[n];

        float smax = sl[0];
#pragma unroll
        for (int n = 1; n < NS; ++n) smax = fmaxf(smax, sl[n]);
        float ssum = 0.f;
#pragma unroll
        for (int n = 0; n < NS; ++n) { sl[n] = __expf(sl[n] - smax); ssum += sl[n]; }
        float sinv = 1.f / ssum;
#pragma unroll
        for (int n = 0; n < NS; ++n) sl[n] *= sinv;

        float fm = fl[0];
#pragma unroll
        for (int n = 1; n < NF; ++n) fm = fmaxf(fm, fl[n]);
        float fsum = 0.f;
#pragma unroll
        for (int n = 0; n < NF; ++n) { fl[n] = __expf(fl[n] - fm); fsum += fl[n]; }
        float finv = 1.f / fsum;
#pragma unroll
        for (int n = 0; n < NF; ++n) fl[n] *= finv;

        const float book = sl[4], change = sl[3];
        long token = (long)blockIdx.x * BM + tid;
        if (token < ntok) {
            float* op = out + token * (long)OUTC;
            op[0] = sl[0];
            op[1] = sl[2];
            op[2] = sl[1];
#pragma unroll
            for (int j = 0; j < NF; ++j) {
                op[3 + j]  = book   * fl[j];
                op[33 + j] = change * fl[j];
            }
        }
    }
}

extern "C" void kernel_launch(void* const* d_in, const int* in_sizes, int n_in,
                              void* d_out, int out_size) {
    const float* embs     = (const float*)d_in[0];
    const float* W_status = (const float*)d_in[1];
    const float* b_status = (const float*)d_in[2];
    const float* W_flight = (const float*)d_in[3];
    const float* b_flight = (const float*)d_in[4];
    float* out = (float*)d_out;

    // pack weights into padded __device__ array (deterministic, capturable)
    pack_w_kernel<<<(NROWS * EMB + 255) / 256, 256>>>(W_status, W_flight);

    int ntok = in_sizes[0] / EMB;   // 65536
    int blocks = ntok / BM;         // 512
    aux2_pf_kernel<<<blocks, NTH>>>(embs, b_status, b_flight, out, ntok);
}